// round 7
// baseline (speedup 1.0000x reference)
#include <cuda_runtime.h>
#include <cuda_bf16.h>

// Cox partial-likelihood loss — single persistent kernel.
//   risk_sum[i] = sum_j exp(theta[j]) * (survtime[j] >= survtime[i])
//   loss = -mean((theta - log(risk_sum)) * censor)
//
// Phase 1: tiled O(N^2) masked reduction (512 blocks, 2 instr/pair via
//          PTX set.ge + FFMA). Partials to fixed slots in __device__ scratch.
// Grid barrier (sense-reversing, all blocks co-resident by construction:
//          8 warps / 32 regs / 1KB smem per block << SM capacity).
// Phase 2: 32 blocks reduce partials -> per-block sums; the LAST finishing
//          block sums those in fixed index order and writes the scalar.
// Deterministic: all FP reductions in fixed order; barrier order is FP-free.
// Graph-capturable: one launch, no allocs, no sync APIs.

#define MAX_N       8192
#define J_TILES     64
#define JCHUNK_MAX  ((MAX_N + J_TILES - 1) / J_TILES)   // 128
#define THREADS     256
#define I_PER_THR   4
#define I_TILE      (THREADS * I_PER_THR)               // 1024
#define MAX_RB      64

// Allocation-free scratch.
__device__ float g_partial[J_TILES * MAX_N];
__device__ float g_bsum[MAX_RB];
__device__ unsigned g_bar_count = 0;
__device__ unsigned g_bar_gen   = 0;
__device__ unsigned g_done      = 0;

__global__ void __launch_bounds__(THREADS)
cox_fused_kernel(const float* __restrict__ y_true,
                 const float* __restrict__ theta,
                 float* __restrict__ out,
                 int N, int jchunk, int rb)
{
    __shared__ float2 sj[JCHUNK_MAX];

    const int itile = blockIdx.x;
    const int jt    = blockIdx.y;
    const int j0    = jt * jchunk;
    int jn = N - j0;
    if (jn > jchunk) jn = jchunk;
    if (jn < 0) jn = 0;

    // ---- Phase 1: partial risk sums -------------------------------------
    for (int j = threadIdx.x; j < jn; j += THREADS) {
        float t = y_true[2 * (j0 + j)];
        float e = __expf(theta[j0 + j]);
        sj[j] = make_float2(t, e);
    }
    __syncthreads();

    const int ibase = itile * I_TILE + threadIdx.x;
    float ti[I_PER_THR];
    #pragma unroll
    for (int k = 0; k < I_PER_THR; ++k) {
        int i = ibase + k * THREADS;
        ti[k] = (i < N) ? y_true[2 * i] : 0.0f;
    }

    float acc[I_PER_THR];
    #pragma unroll
    for (int k = 0; k < I_PER_THR; ++k) acc[k] = 0.0f;

    #pragma unroll 16
    for (int j = 0; j < jn; ++j) {
        float2 v = sj[j];                       // LDS.64 broadcast
        #pragma unroll
        for (int k = 0; k < I_PER_THR; ++k) {
            float m;                            // 1.0f if t_j >= t_i else 0.0f
            asm("set.ge.f32.f32 %0, %1, %2;"    // -> single FSET.BF.GE
                : "=f"(m) : "f"(v.x), "f"(ti[k]));
            acc[k] = fmaf(v.y, m, acc[k]);      // FFMA
        }
    }

    #pragma unroll
    for (int k = 0; k < I_PER_THR; ++k) {
        int i = ibase + k * THREADS;
        if (i < N) g_partial[jt * N + i] = acc[k];
    }

    // Publish phase-1 stores before barrier arrival.
    __threadfence();
    __syncthreads();

    // ---- Grid barrier (sense-reversing) ---------------------------------
    const unsigned nb = gridDim.x * gridDim.y;
    if (threadIdx.x == 0) {
        volatile unsigned* genp = &g_bar_gen;
        unsigned gen = *genp;
        unsigned arrived = atomicAdd(&g_bar_count, 1u);
        if (arrived == nb - 1u) {
            g_bar_count = 0;
            __threadfence();
            atomicExch(&g_bar_gen, gen + 1u);   // release
        } else {
            while (*genp == gen) { __nanosleep(32); }
            __threadfence();                    // acquire
        }
    }
    __syncthreads();

    // ---- Phase 2: contributions (first rb blocks) -----------------------
    const int flat = jt * gridDim.x + itile;
    if (flat >= rb) return;

    __shared__ float red[THREADS];

    const int i = flat * THREADS + threadIdx.x;
    float c = 0.0f;
    if (i < N) {
        float risk = 0.0f;
        #pragma unroll
        for (int t = 0; t < J_TILES; ++t)
            risk += g_partial[t * N + i];
        float censor = (y_true[2 * i + 1] != 0.0f) ? 1.0f : 0.0f;
        c = (theta[i] - __logf(risk)) * censor;
    }

    red[threadIdx.x] = c;
    __syncthreads();
    #pragma unroll
    for (int s = THREADS / 2; s >= 32; s >>= 1) {
        if (threadIdx.x < s) red[threadIdx.x] += red[threadIdx.x + s];
        __syncthreads();
    }
    if (threadIdx.x < 32) {
        float v = red[threadIdx.x];
        #pragma unroll
        for (int o = 16; o > 0; o >>= 1)
            v += __shfl_down_sync(0xFFFFFFFFu, v, o);
        if (threadIdx.x == 0) {
            g_bsum[flat] = v;
            __threadfence();
            unsigned fin = atomicAdd(&g_done, 1u);
            if (fin == (unsigned)rb - 1u) {     // last finisher does final sum
                g_done = 0;
                __threadfence();
                float s = 0.0f;
                for (int b = 0; b < rb; ++b)    // fixed order -> deterministic
                    s += g_bsum[b];
                out[0] = -s / (float)N;
            }
        }
    }
}

// ---------------------------------------------------------------------------
extern "C" void kernel_launch(void* const* d_in, const int* in_sizes, int n_in,
                              void* d_out, int out_size)
{
    // Identify inputs by size: y_true has 2N elements, hazard_pred has N.
    const float* y_true;
    const float* theta;
    int N;
    if (in_sizes[0] == 2 * in_sizes[1]) {
        y_true = (const float*)d_in[0];
        theta  = (const float*)d_in[1];
        N = in_sizes[1];
    } else {
        theta  = (const float*)d_in[0];
        y_true = (const float*)d_in[1];
        N = in_sizes[0];
    }

    float* out = (float*)d_out;

    const int jchunk = (N + J_TILES - 1) / J_TILES;     // 128 for N=8192
    const int itiles = (N + I_TILE - 1) / I_TILE;       // 8   for N=8192
    int rb = (N + THREADS - 1) / THREADS;               // 32  for N=8192
    if (rb > MAX_RB) rb = MAX_RB;                       // (N<=8192 -> never)
    // rb must not exceed grid size; for N>=I_TILE it never does.
    const int nblocks = itiles * J_TILES;
    if (rb > nblocks) rb = nblocks;

    dim3 grid(itiles, J_TILES);
    cox_fused_kernel<<<grid, THREADS>>>(y_true, theta, out, N, jchunk, rb);
}